// round 4
// baseline (speedup 1.0000x reference)
#include <cuda_runtime.h>

// Problem constants (fixed by the dataset instance)
#define D_DIM   1024
#define E_DIM   64
#define TOPK    8
#define B_DIM   4
#define ALPHA   0.1f
#define EPS_R   1e-20f

#define THREADS 512
#define TPB     256      // tokens per block -> grid = 128 (single wave)
#define KC      64       // k-chunk
#define XS_STR  68       // padded smem row stride (floats), 68*4=272B (17x16B)
#define WS_STR  68
#define JT      4        // tokens per thread

// scratch for aux-loss stats (no allocation allowed -> device globals)
__device__ float g_ce[B_DIM * E_DIM];
__device__ float g_ssum[B_DIM * E_DIM];
__device__ unsigned int g_count;

// packed f32x2 FMA: d.lo += a.lo*b.lo; d.hi += a.hi*b.hi  (one issue slot)
__device__ __forceinline__ void fma2(unsigned long long& d,
                                     unsigned long long a,
                                     unsigned long long b) {
    asm("fma.rn.f32x2 %0, %1, %2, %0;" : "+l"(d) : "l"(a), "l"(b));
}

__device__ __forceinline__ float fold2(unsigned long long v) {
    float lo, hi;
    asm("mov.b64 {%0, %1}, %2;" : "=f"(lo), "=f"(hi) : "l"(v));
    return lo + hi;
}

__global__ __launch_bounds__(THREADS, 1)
void moe_gate_kernel(const float* __restrict__ x,
                     const float* __restrict__ W,
                     float* __restrict__ out_idx,
                     float* __restrict__ out_w,
                     float* __restrict__ out_aux,
                     int S, int nblocks)
{
    extern __shared__ float smem_dyn[];
    float* xs = smem_dyn;                       // TPB*XS_STR = 69632 B
    float* ws = smem_dyn + TPB * XS_STR;        // E_DIM*WS_STR = 17408 B

    __shared__ float sm_cnt[E_DIM];
    __shared__ float sm_ssum[E_DIM];
    __shared__ unsigned int sm_ticket;

    const int tid = threadIdx.x;
    const int et  = tid & 7;      // expert lane 0..7  (owns experts et + 8r)
    const int tt  = tid >> 3;     // token thread 0..63 (owns tokens tt + 64j)
    const long t0 = (long)blockIdx.x * TPB;

    float acc[JT][8];   // Kahan running sums
    float cmp[JT][8];   // Kahan compensation
#pragma unroll
    for (int j = 0; j < JT; j++)
#pragma unroll
        for (int r = 0; r < 8; r++) { acc[j][r] = 0.0f; cmp[j][r] = 0.0f; }

    // ---------------- GEMM: logits[tok][e] = x . W[e] ----------------
#pragma unroll 1
    for (int k0 = 0; k0 < D_DIM; k0 += KC) {
        __syncthreads();
        // xs tile: 256 tokens x 64 floats = 4096 float4, 8 per thread
#pragma unroll
        for (int p = 0; p < 8; p++) {
            int idx = tid + THREADS * p;
            int tok = idx >> 4;
            int kq  = idx & 15;
            float4 v = *(const float4*)&x[(t0 + tok) * D_DIM + k0 + kq * 4];
            *(float4*)&xs[tok * XS_STR + kq * 4] = v;
        }
        // ws tile: 64 experts x 64 floats = 1024 float4, 2 per thread
#pragma unroll
        for (int p = 0; p < 2; p++) {
            int idx = tid + THREADS * p;
            int e  = idx >> 4;
            int kq = idx & 15;
            float4 v = *(const float4*)&W[e * D_DIM + k0 + kq * 4];
            *(float4*)&ws[e * WS_STR + kq * 4] = v;
        }
        __syncthreads();

        // two expert half-passes to keep chunk accumulators at 32 regs
#pragma unroll 1
        for (int rh = 0; rh < 2; rh++) {
            unsigned long long cacc2[JT][4];
#pragma unroll
            for (int j = 0; j < JT; j++)
#pragma unroll
                for (int rr = 0; rr < 4; rr++) cacc2[j][rr] = 0ULL;

#pragma unroll
            for (int kq = 0; kq < 16; kq++) {
                ulonglong2 xv[JT];
#pragma unroll
                for (int j = 0; j < JT; j++)
                    xv[j] = *(const ulonglong2*)&xs[(tt + 64 * j) * XS_STR + kq * 4];
#pragma unroll
                for (int rr = 0; rr < 4; rr++) {
                    ulonglong2 wv = *(const ulonglong2*)
                        &ws[(et + 8 * (rh * 4 + rr)) * WS_STR + kq * 4];
#pragma unroll
                    for (int j = 0; j < JT; j++) {
                        fma2(cacc2[j][rr], xv[j].x, wv.x);
                        fma2(cacc2[j][rr], xv[j].y, wv.y);
                    }
                }
            }

            // fold packed partials, Kahan-add into running accumulators
#pragma unroll
            for (int j = 0; j < JT; j++)
#pragma unroll
                for (int rr = 0; rr < 4; rr++) {
                    int r = rh * 4 + rr;
                    float c = fold2(cacc2[j][rr]);
                    float y = c - cmp[j][r];
                    float t = acc[j][r] + y;
                    cmp[j][r] = (t - acc[j][r]) - y;
                    acc[j][r] = t;
                }
        }
    }

    // ---------------- epilogue: softmax + top-8 + stats ----------------
    __syncthreads();
    if (tid < E_DIM) { sm_cnt[tid] = 0.0f; sm_ssum[tid] = 0.0f; }
    __syncthreads();

    const unsigned fullmask = 0xffffffffu;
    float loc_ssum[8];
#pragma unroll
    for (int r = 0; r < 8; r++) loc_ssum[r] = 0.0f;

#pragma unroll 1
    for (int j = 0; j < JT; j++) {
        // softmax over 64 experts split across 8 lanes (et group) x 8 regs
        float m = acc[j][0];
#pragma unroll
        for (int r = 1; r < 8; r++) m = fmaxf(m, acc[j][r]);
#pragma unroll
        for (int d = 1; d < 8; d <<= 1)
            m = fmaxf(m, __shfl_xor_sync(fullmask, m, d));

        float sc[8];
        float s = 0.0f;
#pragma unroll
        for (int r = 0; r < 8; r++) { sc[r] = expf(acc[j][r] - m); s += sc[r]; }
#pragma unroll
        for (int d = 1; d < 8; d <<= 1)
            s += __shfl_xor_sync(fullmask, s, d);
        // exact IEEE division to mirror XLA softmax
#pragma unroll
        for (int r = 0; r < 8; r++) { sc[r] = sc[r] / s; loc_ssum[r] += sc[r]; }

        // iterative top-8 (destructive on sc); tie-break: lower expert index
        float tv[TOPK]; int ti[TOPK];
#pragma unroll 1
        for (int it = 0; it < TOPK; it++) {
            float bv = -1.0f; int bi = E_DIM;
#pragma unroll
            for (int r = 0; r < 8; r++) {
                if (sc[r] > bv) { bv = sc[r]; bi = et + 8 * r; }
            }
#pragma unroll
            for (int d = 1; d < 8; d <<= 1) {
                float ov = __shfl_xor_sync(fullmask, bv, d);
                int   oi = __shfl_xor_sync(fullmask, bi, d);
                if (ov > bv || (ov == bv && oi < bi)) { bv = ov; bi = oi; }
            }
            if ((bi & 7) == et) sc[bi >> 3] = -1.0f;   // owner clears winner
            tv[it] = bv; ti[it] = bi;
        }

        if (et == 0) {
            float wsum = 0.0f;
#pragma unroll
            for (int it = 0; it < TOPK; it++) wsum += tv[it];
            wsum += EPS_R;
            long t = t0 + tt + 64 * j;
#pragma unroll
            for (int it = 0; it < TOPK; it++) {
                out_idx[t * TOPK + it] = (float)ti[it];
                out_w  [t * TOPK + it] = tv[it] / wsum;
                atomicAdd(&sm_cnt[ti[it]], 1.0f);
            }
        }
    }

#pragma unroll
    for (int r = 0; r < 8; r++)
        atomicAdd(&sm_ssum[et + 8 * r], loc_ssum[r]);
    __syncthreads();

    if (tid < E_DIM) {
        int b = (int)(t0 / (long)S);           // block is batch-aligned (256 | 8192)
        atomicAdd(&g_ce[b * E_DIM + tid],   sm_cnt[tid]);
        atomicAdd(&g_ssum[b * E_DIM + tid], sm_ssum[tid]);
    }

    // ---------------- fused aux finalization (last CTA) ----------------
    __threadfence();
    if (tid == 0) sm_ticket = atomicAdd(&g_count, 1u);
    __syncthreads();

    if (sm_ticket == (unsigned)(nblocks - 1)) {
        __threadfence();
        float v = 0.0f;
        if (tid < B_DIM * E_DIM) {
            const volatile float* ce = g_ce;
            const volatile float* ss = g_ssum;
            v = ce[tid] * ss[tid];
        }
        // reduce 512 values (only first 256 nonzero) using xs as scratch
        float* red = xs;
        red[tid] = v;
        __syncthreads();
        for (int off = 256; off > 0; off >>= 1) {
            if (tid < off) red[tid] += red[tid + off];
            __syncthreads();
        }
        if (tid == 0)
            out_aux[0] = red[0] / (float)S / (float)B_DIM * ALPHA;
        // reset scratch for the next graph replay
        if (tid < B_DIM * E_DIM) { g_ce[tid] = 0.0f; g_ssum[tid] = 0.0f; }
        if (tid == 0) g_count = 0u;
    }
}

extern "C" void kernel_launch(void* const* d_in, const int* in_sizes, int n_in,
                              void* d_out, int out_size) {
    const float* x = (const float*)d_in[0];
    const float* W = (const float*)d_in[1];
    const int T = in_sizes[0] / D_DIM;     // 32768
    const int S = T / B_DIM;               // 8192
    const int nblocks = T / TPB;           // 128

    float* out     = (float*)d_out;
    float* out_idx = out;                         // [T,8] indices as float
    float* out_w   = out + (size_t)T * TOPK;      // [T,8] weights
    float* out_aux = out + (out_size - 1);        // scalar aux loss

    const int smem_bytes = (TPB * XS_STR + E_DIM * WS_STR) * (int)sizeof(float);
    cudaFuncSetAttribute(moe_gate_kernel,
                         cudaFuncAttributeMaxDynamicSharedMemorySize, smem_bytes);
    moe_gate_kernel<<<nblocks, THREADS, smem_bytes>>>(x, W, out_idx, out_w,
                                                      out_aux, S, nblocks);
}

// round 6
// speedup vs baseline: 5.0294x; 5.0294x over previous
#include <cuda_runtime.h>

// Problem constants (fixed by the dataset instance)
#define D_DIM   1024
#define E_DIM   64
#define TOPK    8
#define B_DIM   4
#define ALPHA   0.1f
#define EPS_R   1e-20f

#define THREADS 128
#define TPB     64       // tokens per tile
#define NTILES  2        // tiles per CTA (persistent)
#define KC      64       // k-chunk
#define NCHUNK  (D_DIM / KC)          // 16
#define ROW_STR 68       // padded smem row stride (floats); 68*4=272B (17x16B)
#define TILE_FL (TPB * ROW_STR + E_DIM * ROW_STR)   // 8704 floats per buffer
#define JT      4        // tokens per thread

// scratch for aux-loss stats (no allocation allowed -> device globals)
__device__ float g_ce[B_DIM * E_DIM];
__device__ float g_ssum[B_DIM * E_DIM];
__device__ unsigned int g_count;

// packed f32x2 FMA: d.lo += a.lo*b.lo; d.hi += a.hi*b.hi  (one issue slot)
__device__ __forceinline__ void fma2(unsigned long long& d,
                                     unsigned long long a,
                                     unsigned long long b) {
    asm("fma.rn.f32x2 %0, %1, %2, %0;" : "+l"(d) : "l"(a), "l"(b));
}

__device__ __forceinline__ float fold2(unsigned long long v) {
    float lo, hi;
    asm("mov.b64 {%0, %1}, %2;" : "=f"(lo), "=f"(hi) : "l"(v));
    return lo + hi;
}

__device__ __forceinline__ void cp16(unsigned dst, const void* src) {
    asm volatile("cp.async.ca.shared.global [%0], [%1], 16;\n"
                 :: "r"(dst), "l"(src));
}
__device__ __forceinline__ void cp_commit() {
    asm volatile("cp.async.commit_group;\n");
}
template <int N>
__device__ __forceinline__ void cp_wait() {
    asm volatile("cp.async.wait_group %0;\n" :: "n"(N));
}

__global__ __launch_bounds__(THREADS, 2)
void moe_gate_kernel(const float* __restrict__ x,
                     const float* __restrict__ W,
                     float* __restrict__ out_idx,
                     float* __restrict__ out_w,
                     float* __restrict__ out_aux,
                     int S, int nblocks)
{
    extern __shared__ float smem_dyn[];   // 2 * TILE_FL floats (double buffer)
    __shared__ float sm_cnt[E_DIM];
    __shared__ float sm_ssum[E_DIM];
    __shared__ unsigned int sm_ticket;

    const unsigned sbase = (unsigned)__cvta_generic_to_shared(smem_dyn);
    const int tid = threadIdx.x;
    const int et  = tid & 7;      // expert lane 0..7  (owns experts et + 8r)
    const int tt  = tid >> 3;     // token thread 0..15 (owns tokens tt + 16j)
    const unsigned fullmask = 0xffffffffu;

#pragma unroll 1
    for (int tile = 0; tile < NTILES; tile++) {
        const long t0 = (long)(blockIdx.x + tile * nblocks) * TPB;

        float acc[JT][8];   // Kahan running sums
        float cmp[JT][8];   // Kahan compensation
#pragma unroll
        for (int j = 0; j < JT; j++)
#pragma unroll
            for (int r = 0; r < 8; r++) { acc[j][r] = 0.0f; cmp[j][r] = 0.0f; }

        // -------- prefetch chunk 0 --------
        {
            const int k0 = 0;
            const unsigned xb = sbase;                       // buffer 0
            const unsigned wb = sbase + TPB * ROW_STR * 4;
            // x tile: 64 tokens x 16 float4 = 1024 f4 -> 8 per thread
#pragma unroll
            for (int p = 0; p < 8; p++) {
                int idx = tid + THREADS * p;
                int tok = idx >> 4, kq = idx & 15;
                cp16(xb + (tok * ROW_STR + kq * 4) * 4,
                     &x[(t0 + tok) * D_DIM + k0 + kq * 4]);
            }
            // W tile: 64 experts x 16 float4 = 1024 f4 -> 8 per thread
#pragma unroll
            for (int p = 0; p < 8; p++) {
                int idx = tid + THREADS * p;
                int e = idx >> 4, kq = idx & 15;
                cp16(wb + (e * ROW_STR + kq * 4) * 4,
                     &W[e * D_DIM + k0 + kq * 4]);
            }
            cp_commit();
        }

        // ---------------- GEMM main loop ----------------
#pragma unroll 1
        for (int c = 0; c < NCHUNK; c++) {
            if (c + 1 < NCHUNK) {
                const int k0 = (c + 1) * KC;
                const unsigned buf = ((unsigned)(c + 1) & 1u) * TILE_FL * 4;
                const unsigned xb = sbase + buf;
                const unsigned wb = xb + TPB * ROW_STR * 4;
#pragma unroll
                for (int p = 0; p < 8; p++) {
                    int idx = tid + THREADS * p;
                    int tok = idx >> 4, kq = idx & 15;
                    cp16(xb + (tok * ROW_STR + kq * 4) * 4,
                         &x[(t0 + tok) * D_DIM + k0 + kq * 4]);
                }
#pragma unroll
                for (int p = 0; p < 8; p++) {
                    int idx = tid + THREADS * p;
                    int e = idx >> 4, kq = idx & 15;
                    cp16(wb + (e * ROW_STR + kq * 4) * 4,
                         &W[e * D_DIM + k0 + kq * 4]);
                }
                cp_commit();
                cp_wait<1>();   // wait for chunk c; chunk c+1 stays in flight
            } else {
                cp_wait<0>();
            }
            __syncthreads();

            const float* xb = smem_dyn + (c & 1) * TILE_FL;
            const float* wb = xb + TPB * ROW_STR;

            unsigned long long cacc2[JT][8];
#pragma unroll
            for (int j = 0; j < JT; j++)
#pragma unroll
                for (int r = 0; r < 8; r++) cacc2[j][r] = 0ULL;

#pragma unroll
            for (int kq = 0; kq < 16; kq++) {
                ulonglong2 xv[JT], wv[8];
#pragma unroll
                for (int j = 0; j < JT; j++)
                    xv[j] = *(const ulonglong2*)&xb[(tt + 16 * j) * ROW_STR + kq * 4];
#pragma unroll
                for (int r = 0; r < 8; r++)
                    wv[r] = *(const ulonglong2*)&wb[(et + 8 * r) * ROW_STR + kq * 4];
#pragma unroll
                for (int j = 0; j < JT; j++)
#pragma unroll
                    for (int r = 0; r < 8; r++) {
                        fma2(cacc2[j][r], xv[j].x, wv[r].x);
                        fma2(cacc2[j][r], xv[j].y, wv[r].y);
                    }
            }

            // fold packed partials, Kahan-add into running accumulators
#pragma unroll
            for (int j = 0; j < JT; j++)
#pragma unroll
                for (int r = 0; r < 8; r++) {
                    float cs = fold2(cacc2[j][r]);
                    float y = cs - cmp[j][r];
                    float t = acc[j][r] + y;
                    cmp[j][r] = (t - acc[j][r]) - y;
                    acc[j][r] = t;
                }
            __syncthreads();   // buffer (c&1) is cp.async target in iter c+1
        }

        // ---------------- epilogue: softmax + top-8 + stats ----------------
        if (tid < E_DIM) { sm_cnt[tid] = 0.0f; sm_ssum[tid] = 0.0f; }
        __syncthreads();

        float loc_ssum[8];
#pragma unroll
        for (int r = 0; r < 8; r++) loc_ssum[r] = 0.0f;

#pragma unroll 1
        for (int j = 0; j < JT; j++) {
            // softmax over 64 experts split across 8 lanes (et) x 8 regs
            float m = acc[j][0];
#pragma unroll
            for (int r = 1; r < 8; r++) m = fmaxf(m, acc[j][r]);
#pragma unroll
            for (int d = 1; d < 8; d <<= 1)
                m = fmaxf(m, __shfl_xor_sync(fullmask, m, d));

            float sc[8];
            float s = 0.0f;
#pragma unroll
            for (int r = 0; r < 8; r++) { sc[r] = expf(acc[j][r] - m); s += sc[r]; }
#pragma unroll
            for (int d = 1; d < 8; d <<= 1)
                s += __shfl_xor_sync(fullmask, s, d);
            // exact IEEE division to mirror XLA softmax
#pragma unroll
            for (int r = 0; r < 8; r++) { sc[r] = sc[r] / s; loc_ssum[r] += sc[r]; }

            // iterative top-8 (destructive on sc); tie-break: lower index
            float tv[TOPK]; int ti[TOPK];
#pragma unroll 1
            for (int it = 0; it < TOPK; it++) {
                float bv = -1.0f; int bi = E_DIM;
#pragma unroll
                for (int r = 0; r < 8; r++) {
                    if (sc[r] > bv) { bv = sc[r]; bi = et + 8 * r; }
                }
#pragma unroll
                for (int d = 1; d < 8; d <<= 1) {
                    float ov = __shfl_xor_sync(fullmask, bv, d);
                    int   oi = __shfl_xor_sync(fullmask, bi, d);
                    if (ov > bv || (ov == bv && oi < bi)) { bv = ov; bi = oi; }
                }
                if ((bi & 7) == et) sc[bi >> 3] = -1.0f;   // owner clears winner
                tv[it] = bv; ti[it] = bi;
            }

            if (et == 0) {
                float wsum = 0.0f;
#pragma unroll
                for (int it = 0; it < TOPK; it++) wsum += tv[it];
                wsum += EPS_R;
                long t = t0 + tt + 16 * j;
#pragma unroll
                for (int it = 0; it < TOPK; it++) {
                    out_idx[t * TOPK + it] = (float)ti[it];
                    out_w  [t * TOPK + it] = tv[it] / wsum;
                    atomicAdd(&sm_cnt[ti[it]], 1.0f);
                }
            }
        }

#pragma unroll
        for (int r = 0; r < 8; r++)
            atomicAdd(&sm_ssum[et + 8 * r], loc_ssum[r]);
        __syncthreads();

        if (tid < E_DIM) {
            int b = (int)(t0 / (long)S);       // tile is batch-aligned (64 | 8192)
            atomicAdd(&g_ce[b * E_DIM + tid],   sm_cnt[tid]);
            atomicAdd(&g_ssum[b * E_DIM + tid], sm_ssum[tid]);
        }
        __syncthreads();
    }

    // ---------------- fused aux finalization (last CTA) ----------------
    __threadfence();
    if (tid == 0) sm_ticket = atomicAdd(&g_count, 1u);
    __syncthreads();

    if (sm_ticket == (unsigned)(nblocks - 1)) {
        __threadfence();
        const volatile float* ce = g_ce;
        const volatile float* ss = g_ssum;
        float v = ce[tid] * ss[tid] + ce[tid + 128] * ss[tid + 128];
        float* red = smem_dyn;
        red[tid] = v;
        __syncthreads();
        for (int off = 64; off > 0; off >>= 1) {
            if (tid < off) red[tid] += red[tid + off];
            __syncthreads();
        }
        if (tid == 0)
            out_aux[0] = red[0] / (float)S / (float)B_DIM * ALPHA;
        // reset scratch for the next graph replay
        if (tid < 128) { g_ce[tid] = 0.0f; g_ssum[tid] = 0.0f;
                         g_ce[tid + 128] = 0.0f; g_ssum[tid + 128] = 0.0f; }
        if (tid == 0) g_count = 0u;
    }
}

extern "C" void kernel_launch(void* const* d_in, const int* in_sizes, int n_in,
                              void* d_out, int out_size) {
    const float* x = (const float*)d_in[0];
    const float* W = (const float*)d_in[1];
    const int T = in_sizes[0] / D_DIM;       // 32768
    const int S = T / B_DIM;                 // 8192
    const int nblocks = T / (TPB * NTILES);  // 256 (single wave at 2 CTA/SM)

    float* out     = (float*)d_out;
    float* out_idx = out;                         // [T,8] indices as float
    float* out_w   = out + (size_t)T * TOPK;      // [T,8] weights
    float* out_aux = out + (out_size - 1);        // scalar aux loss

    const int smem_bytes = 2 * TILE_FL * (int)sizeof(float);  // ~69.6 KB
    cudaFuncSetAttribute(moe_gate_kernel,
                         cudaFuncAttributeMaxDynamicSharedMemorySize, smem_bytes);
    moe_gate_kernel<<<nblocks, THREADS, smem_bytes>>>(x, W, out_idx, out_w,
                                                      out_aux, S, nblocks);
}